// round 11
// baseline (speedup 1.0000x reference)
#include <cuda_runtime.h>
#include <cuda_fp16.h>

#define NN  100000
#define EE  3200000
#define FIN 256
#define HID 16
#define CC  40
#define NB_SCAN 98   // ceil(100000/1024)

// ---------------- scratch (device globals; no allocation) ----------------
__device__ int   g_deg[NN];
__device__ float g_dinv[NN];
__device__ int   g_rowptr[NN + 1];
__device__ int   g_cursor[NN];
__device__ int   g_col[EE];
__device__ float g_P[NN * HID];                 // x@W1 (fp32, unscaled)
__device__ __align__(32) uint2 g_Ph[NN * 4];    // dinv*P packed fp16 (32B/node row)
__device__ __align__(32) uint2 g_Hh[NN * 4];    // dinv-scaled relu hidden, fp16
__device__ int   g_bsum[NB_SCAN];
__device__ int   g_is64;

// ---------------- helpers ----------------
__device__ __forceinline__ void h8_acc(uint2 p, float4& acc) {
    float2 lo = __half22float2(*(__half2*)&p.x);
    float2 hi = __half22float2(*(__half2*)&p.y);
    acc.x += lo.x; acc.y += lo.y; acc.z += hi.x; acc.w += hi.y;
}
__device__ __forceinline__ uint2 f4_to_h8(float4 v) {
    __half2 h0 = __floats2half2_rn(v.x, v.y);
    __half2 h1 = __floats2half2_rn(v.z, v.w);
    uint2 o;
    o.x = *(unsigned*)&h0;
    o.y = *(unsigned*)&h1;
    return o;
}

// ---------------- init: zero degrees + edge dtype detection ----------------
// int64 little-endian nonneg values < 2^31 => every odd 32-bit word is 0.
__global__ void k_init(const int* __restrict__ p) {
    int i = blockIdx.x * blockDim.x + threadIdx.x;
    if (i < NN) g_deg[i] = 0;
    if (i == 0) {
        int z = 0;
        #pragma unroll
        for (int k = 1; k < 64; k += 2) z |= p[k];
        g_is64 = (z == 0) ? 1 : 0;
    }
}

// ---------------- degree count: 2 edges per thread, vector loads ----------------
__global__ void k_deg(const void* __restrict__ eip) {
    int t = blockIdx.x * blockDim.x + threadIdx.x;   // t < EE/2
    if (t >= EE / 2) return;
    if (g_is64) {
        longlong2 v = ((const longlong2*)((const long long*)eip + EE))[t];
        atomicAdd(&g_deg[(int)v.x], 1);
        atomicAdd(&g_deg[(int)v.y], 1);
    } else {
        int2 v = ((const int2*)((const int*)eip + EE))[t];
        atomicAdd(&g_deg[v.x], 1);
        atomicAdd(&g_deg[v.y], 1);
    }
}

// ---------------- block scan (warp-shuffle based) ----------------
// writes block-exclusive prefix into g_cursor, block total into g_bsum
__global__ void __launch_bounds__(1024) k_scan1() {
    __shared__ int wsum[32];
    int t = threadIdx.x;
    int i = blockIdx.x * 1024 + t;
    int d = (i < NN) ? g_deg[i] : 0;
    int v = d;
    #pragma unroll
    for (int off = 1; off < 32; off <<= 1) {
        int n = __shfl_up_sync(0xffffffffu, v, off);
        if ((t & 31) >= off) v += n;
    }
    if ((t & 31) == 31) wsum[t >> 5] = v;
    __syncthreads();
    if (t < 32) {
        int w = wsum[t];
        #pragma unroll
        for (int off = 1; off < 32; off <<= 1) {
            int n = __shfl_up_sync(0xffffffffu, w, off);
            if (t >= off) w += n;
        }
        wsum[t] = w;
    }
    __syncthreads();
    int base = (t >= 32) ? wsum[(t >> 5) - 1] : 0;
    int incl = v + base;
    if (i < NN) g_cursor[i] = incl - d;
    if (t == 1023) g_bsum[blockIdx.x] = incl;   // block TOTAL (unscanned)
}

// ---------------- fused scan finalize (replaces scan2 + scan3) ----------------
// Each block parallel-reduces the <=97 preceding block totals (tree reduce,
// NOT the serial thread-0 loop that failed in R5), then finalizes
// rowptr / cursor / dinv for its 512 nodes.
__global__ void __launch_bounds__(512) k_scan3() {
    __shared__ int red[512];
    int t = threadIdx.x;
    int chunk = blockIdx.x >> 1;                  // = (i >> 10) for all i in block
    red[t] = (t < chunk) ? g_bsum[t] : 0;         // chunk <= 97 < 512
    __syncthreads();
    #pragma unroll
    for (int off = 256; off >= 1; off >>= 1) {
        if (t < off) red[t] += red[t + off];
        __syncthreads();
    }
    int sbase = red[0];
    int i = blockIdx.x * 512 + t;
    if (i < NN) {
        int s = g_cursor[i] + sbase;
        g_rowptr[i] = s;
        g_cursor[i] = s;
        g_dinv[i]   = rsqrtf((float)g_deg[i] + 1.0f);  // +1 self-loop
        if (i == NN - 1) g_rowptr[NN] = s + g_deg[i];  // == EE
    }
}

// ---------------- CSR fill: 2 edges per thread, vector loads ----------------
__global__ void k_fill(const void* __restrict__ eip) {
    int t = blockIdx.x * blockDim.x + threadIdx.x;   // t < EE/2
    if (t >= EE / 2) return;
    if (g_is64) {
        longlong2 s = ((const longlong2*)eip)[t];
        longlong2 d = ((const longlong2*)((const long long*)eip + EE))[t];
        int p0 = atomicAdd(&g_cursor[(int)d.x], 1);
        g_col[p0] = (int)s.x;
        int p1 = atomicAdd(&g_cursor[(int)d.y], 1);
        g_col[p1] = (int)s.y;
    } else {
        int2 s = ((const int2*)eip)[t];
        int2 d = ((const int2*)((const int*)eip + EE))[t];
        int p0 = atomicAdd(&g_cursor[d.x], 1);
        g_col[p0] = s.x;
        int p1 = atomicAdd(&g_cursor[d.y], 1);
        g_col[p1] = s.y;
    }
}

// ---------------- GEMM: g_P = x @ W1 (unscaled fp32), [N,16] ----------------
// LDS-economy: 128 rows/block, K chunked by 64, 4 rows x 4 cols per thread.
// Rows strided by 32 -> every x LDS.128 is 8 unique 16B addrs = 1 wavefront.
#define RB 128          // rows per block
#define KC 64           // k-chunk
#define XP 17           // xs pitch in float4 units (16 data + 1 pad)
__global__ void __launch_bounds__(128) k_gemm(const float* __restrict__ x,
                                              const float* __restrict__ W1) {
    __shared__ float4 xs[RB * XP];           // 34816 B
    __shared__ float4 ws[KC * HID / 4];      // 4096 B
    int tid = threadIdx.x;
    int rg = tid >> 2, jg = tid & 3;         // rg in [0,32), jg in [0,4)
    int base = blockIdx.x * RB;

    float4 acc[4];
    #pragma unroll
    for (int r = 0; r < 4; r++) acc[r] = make_float4(0.f, 0.f, 0.f, 0.f);

    const float4* x4 = (const float4*)x;
    const float4* W4 = (const float4*)W1;

    for (int c = 0; c < FIN / KC; c++) {
        #pragma unroll
        for (int q = tid; q < KC * HID / 4; q += 128)
            ws[q] = W4[c * (KC * HID / 4) + q];
        #pragma unroll
        for (int q = tid; q < RB * (KC / 4); q += 128) {
            int row = q >> 4, f4i = q & 15;
            int grow = base + row;
            float4 v = make_float4(0.f, 0.f, 0.f, 0.f);
            if (grow < NN) v = x4[(size_t)grow * (FIN / 4) + c * (KC / 4) + f4i];
            xs[row * XP + f4i] = v;
        }
        __syncthreads();

        #pragma unroll
        for (int k4 = 0; k4 < KC / 4; k4++) {
            float4 w0 = ws[(k4 * 4 + 0) * 4 + jg];
            float4 w1 = ws[(k4 * 4 + 1) * 4 + jg];
            float4 w2 = ws[(k4 * 4 + 2) * 4 + jg];
            float4 w3 = ws[(k4 * 4 + 3) * 4 + jg];
            #pragma unroll
            for (int r = 0; r < 4; r++) {
                float4 xv = xs[(rg + 32 * r) * XP + k4];
                acc[r].x += xv.x * w0.x + xv.y * w1.x + xv.z * w2.x + xv.w * w3.x;
                acc[r].y += xv.x * w0.y + xv.y * w1.y + xv.z * w2.y + xv.w * w3.y;
                acc[r].z += xv.x * w0.z + xv.y * w1.z + xv.z * w2.z + xv.w * w3.z;
                acc[r].w += xv.x * w0.w + xv.y * w1.w + xv.z * w2.w + xv.w * w3.w;
            }
        }
        __syncthreads();
    }

    #pragma unroll
    for (int r = 0; r < 4; r++) {
        int row = base + rg + 32 * r;
        if (row < NN) ((float4*)g_P)[(size_t)row * 4 + jg] = acc[r];
    }
}

// ---------------- P' = dinv * P, packed to fp16 (overlaps k_fill) ----------------
__global__ void __launch_bounds__(512) k_scaleP() {
    int t = blockIdx.x * 512 + threadIdx.x;   // t < NN*4 (float4 index)
    if (t < NN * 4) {
        float di = g_dinv[t >> 2];
        float4 v = ((const float4*)g_P)[t];
        v.x *= di; v.y *= di; v.z *= di; v.w *= di;
        g_Ph[t] = f4_to_h8(v);
    }
}

// ---------------- Layer-1 aggregation (warp-per-node, fp16 gather) ----------------
// H' = dinv * relu(dinv*(sum P'[col] + P'[i]) + b1)   (P' pre-scaled by dinv)
__global__ void __launch_bounds__(256) k_agg1(const float* __restrict__ bias) {
    int warp = threadIdx.x >> 5;
    int lane = threadIdx.x & 31;
    int el = lane >> 2, c = lane & 3;
    int i = blockIdx.x * 8 + warp;        // grid exact: 12500*8 == NN

    int e0 = g_rowptr[i];
    int e1 = g_rowptr[i + 1];
    float4 acc = make_float4(0.f, 0.f, 0.f, 0.f);
    for (int e = e0 + el; e < e1; e += 8) {
        int s = g_col[e];
        h8_acc(g_Ph[(size_t)s * 4 + c], acc);
    }
    #pragma unroll
    for (int off = 16; off >= 4; off >>= 1) {
        acc.x += __shfl_down_sync(0xffffffffu, acc.x, off);
        acc.y += __shfl_down_sync(0xffffffffu, acc.y, off);
        acc.z += __shfl_down_sync(0xffffffffu, acc.z, off);
        acc.w += __shfl_down_sync(0xffffffffu, acc.w, off);
    }
    if (el == 0) {
        h8_acc(g_Ph[(size_t)i * 4 + c], acc);       // self-loop (pre-scaled)
        float di = g_dinv[i];
        float4 b = ((const float4*)bias)[c];
        float4 v;
        v.x = fmaxf(acc.x * di + b.x, 0.f) * di;
        v.y = fmaxf(acc.y * di + b.y, 0.f) * di;
        v.z = fmaxf(acc.z * di + b.z, 0.f) * di;
        v.w = fmaxf(acc.w * di + b.w, 0.f) * di;
        g_Hh[(size_t)i * 4 + c] = f4_to_h8(v);
    }
}

// ---------------- Fused layer-2 agg + W2 + bias + log_softmax + store ----------------
__global__ void __launch_bounds__(256) k_agg2_final(const float* __restrict__ W2,
                                                    const float* __restrict__ b2,
                                                    float* __restrict__ out) {
    __shared__ float w2s[HID * CC];
    __shared__ float b2s[CC];
    __shared__ float gsm[8][16];
    int tid = threadIdx.x;
    for (int q = tid; q < HID * CC; q += 256) w2s[q] = W2[q];
    if (tid < CC) b2s[tid] = b2[tid];
    __syncthreads();

    int warp = tid >> 5, lane = tid & 31;
    int el = lane >> 2, c = lane & 3;
    int i = blockIdx.x * 8 + warp;        // grid exact

    int e0 = g_rowptr[i];
    int e1 = g_rowptr[i + 1];
    float4 acc = make_float4(0.f, 0.f, 0.f, 0.f);
    for (int e = e0 + el; e < e1; e += 8) {
        int s = g_col[e];
        h8_acc(g_Hh[(size_t)s * 4 + c], acc);
    }
    #pragma unroll
    for (int off = 16; off >= 4; off >>= 1) {
        acc.x += __shfl_down_sync(0xffffffffu, acc.x, off);
        acc.y += __shfl_down_sync(0xffffffffu, acc.y, off);
        acc.z += __shfl_down_sync(0xffffffffu, acc.z, off);
        acc.w += __shfl_down_sync(0xffffffffu, acc.w, off);
    }
    if (el == 0) {
        h8_acc(g_Hh[(size_t)i * 4 + c], acc);
        float di = g_dinv[i];
        gsm[warp][c * 4 + 0] = acc.x * di;
        gsm[warp][c * 4 + 1] = acc.y * di;
        gsm[warp][c * 4 + 2] = acc.z * di;
        gsm[warp][c * 4 + 3] = acc.w * di;
    }
    __syncwarp();

    float g[HID];
    #pragma unroll
    for (int f = 0; f < HID; f++) g[f] = gsm[warp][f];

    float a0 = b2s[lane];
    #pragma unroll
    for (int f = 0; f < HID; f++) a0 += g[f] * w2s[f * CC + lane];
    float a1 = -1e30f;
    if (lane < 8) {
        a1 = b2s[lane + 32];
        #pragma unroll
        for (int f = 0; f < HID; f++) a1 += g[f] * w2s[f * CC + lane + 32];
    }

    float m = fmaxf(a0, a1);
    #pragma unroll
    for (int off = 16; off >= 1; off >>= 1)
        m = fmaxf(m, __shfl_xor_sync(0xffffffffu, m, off));
    float s = __expf(a0 - m) + ((lane < 8) ? __expf(a1 - m) : 0.f);
    #pragma unroll
    for (int off = 16; off >= 1; off >>= 1)
        s += __shfl_xor_sync(0xffffffffu, s, off);
    float lse = m + __logf(s);

    out[(size_t)i * CC + lane] = a0 - lse;
    if (lane < 8) out[(size_t)i * CC + lane + 32] = a1 - lse;
}

// ---------------- launch ----------------
extern "C" void kernel_launch(void* const* d_in, const int* in_sizes, int n_in,
                              void* d_out, int out_size) {
    const float* x  = (const float*)d_in[0];
    const void*  ei = (const void*)d_in[1];   // int64 or int32, detected on device
    const float* W1 = (const float*)d_in[2];
    const float* b1 = (const float*)d_in[3];
    const float* W2 = (const float*)d_in[4];
    const float* b2 = (const float*)d_in[5];
    float* out = (float*)d_out;

    // lazily created once (outside capture, during the correctness run)
    static cudaStream_t s2 = nullptr;
    static cudaEvent_t ev_fork = nullptr, ev_scan3 = nullptr, ev_scaled = nullptr;
    if (!s2) {
        cudaStreamCreateWithFlags(&s2, cudaStreamNonBlocking);
        cudaEventCreateWithFlags(&ev_fork,   cudaEventDisableTiming);
        cudaEventCreateWithFlags(&ev_scan3,  cudaEventDisableTiming);
        cudaEventCreateWithFlags(&ev_scaled, cudaEventDisableTiming);
    }

    // fork: gemm branch (independent of edge processing)
    cudaEventRecord(ev_fork, 0);
    cudaStreamWaitEvent(s2, ev_fork, 0);
    k_gemm<<<(NN + RB - 1) / RB, 128, 0, s2>>>(x, W1);

    // main branch: CSR construction
    k_init<<<(NN + 511) / 512, 512>>>((const int*)ei);
    k_deg<<<(EE / 2 + 255) / 256, 256>>>(ei);
    k_scan1<<<NB_SCAN, 1024>>>();
    k_scan3<<<(NN + 511) / 512, 512>>>();
    cudaEventRecord(ev_scan3, 0);
    k_fill<<<(EE / 2 + 255) / 256, 256>>>(ei);

    // scaleP on gemm branch (needs gemm + scan3), overlaps k_fill
    cudaStreamWaitEvent(s2, ev_scan3, 0);
    k_scaleP<<<(NN * 4 + 511) / 512, 512, 0, s2>>>();
    cudaEventRecord(ev_scaled, s2);
    cudaStreamWaitEvent(0, ev_scaled, 0);

    // join: aggregations
    k_agg1<<<NN / 8, 256>>>(b1);
    k_agg2_final<<<NN / 8, 256>>>(W2, b2, out);
}